// round 16
// baseline (speedup 1.0000x reference)
#include <cuda_runtime.h>
#include <cuda_fp16.h>
#include <cstdint>
#include <cstddef>

// ---------------- problem dims (fixed) ----------------
#define M_TOTAL 16384   // B*S = 4*4096
#define N_TOTAL 4096    // DOUT
#define K_TOTAL 1024    // DIN

// ---------------- GEMM tiling: 128x128x32, 4 warps, warp tile 64x64 --------
// R15 (346us, tensor=69%) showed ~30% tensor-pipe idle with 2 warps/SMSP.
// This round: BK 64->32, single-buffered frags (B in two 8-reg halves) to fit
// regs<=170 and smem<=61.6KB -> 3 CTAs/SM = 3 warps/SMSP for bubble coverage.
#define BM 128
#define BN 128
#define BK 32
#define NKT (K_TOTAL / BK)        // 32 mainloop iterations
#define STAGES 3
#define THREADS 128               // 4 warps, 2x2 grid, warp tile 64x64

// smem row stride: BK+8 halfs = 80 bytes. gcd(80,128)=16 -> the 8 rows of each
// ldmatrix phase hit 8 distinct 16B slots mod 128B => conflict-free.
#define ROW_B 80
#define A_STG (BM * ROW_B)        // 10240 B
#define B_STG (BN * ROW_B)        // 10240 B
#define STG_BYTES (A_STG + B_STG) // 20480 B
#define OFF_FULL  0               // full[0..2]  mbarriers (8B each)
#define OFF_EMPTY 24              // empty[0..2] mbarriers
#define OFF_STG   128
#define OFF_A 0
#define OFF_B A_STG
#define SMEM_TOTAL (OFF_STG + STAGES * STG_BYTES)   // 61568 -> 3 CTAs/SM

// ---------------- scratch (device globals; allocation forbidden) -----------
__device__ __align__(128) __half g_A[(size_t)M_TOTAL * K_TOTAL];  // 32 MB fp16 input
__device__ __align__(128) __half g_B[(size_t)N_TOTAL * K_TOTAL];  // 8 MB fp16 {0,1} mask
__device__ float g_rowsum[M_TOTAL];

// ---------------- PTX helpers ----------------
__device__ __forceinline__ uint32_t smem_u32(const void* p) {
    uint32_t a;
    asm("{ .reg .u64 t; cvta.to.shared.u64 t, %1; cvt.u32.u64 %0, t; }" : "=r"(a) : "l"(p));
    return a;
}

__device__ __forceinline__ void cp_async16(uint32_t saddr, const void* g) {
    asm volatile("cp.async.cg.shared.global [%0], [%1], 16;" :: "r"(saddr), "l"(g) : "memory");
}

#define MBAR_INIT(addr, cnt)                                                    \
    asm volatile("mbarrier.init.shared.b64 [%0], %1;"                           \
                 :: "r"((uint32_t)(addr)), "r"((uint32_t)(cnt)) : "memory")

#define MBAR_ARRIVE(addr)                                                       \
    asm volatile("mbarrier.arrive.shared.b64 _, [%0];"                          \
                 :: "r"((uint32_t)(addr)) : "memory")

// .noinc: this thread's prior cp.asyncs perform ONE real arrive (consuming the
// init count) on the mbarrier when they complete.
#define CP_ASYNC_MBAR_ARRIVE(addr)                                              \
    asm volatile("cp.async.mbarrier.arrive.noinc.shared.b64 [%0];"              \
                 :: "r"((uint32_t)(addr)) : "memory")

#define MBAR_WAIT_PARITY(addr, par) do {                                        \
    uint32_t _mb = (uint32_t)(addr);                                            \
    uint32_t _p  = (uint32_t)(par);                                             \
    asm volatile(                                                               \
        "{\n\t"                                                                 \
        ".reg .pred P1;\n\t"                                                    \
        "WAIT_LOOP_%=:\n\t"                                                     \
        "mbarrier.try_wait.parity.acquire.cta.shared::cta.b64 P1, [%0], %1, 0x989680;\n\t" \
        "@P1 bra.uni WAIT_DONE_%=;\n\t"                                         \
        "bra.uni WAIT_LOOP_%=;\n\t"                                             \
        "WAIT_DONE_%=:\n\t"                                                     \
        "}" :: "r"(_mb), "r"(_p) : "memory");                                   \
} while (0)

#define LDSM4(r0, r1, r2, r3, addr)                                             \
    asm volatile("ldmatrix.sync.aligned.m8n8.x4.shared.b16 {%0,%1,%2,%3}, [%4];" \
                 : "=r"(r0), "=r"(r1), "=r"(r2), "=r"(r3) : "r"(addr))

#define MMA16816(d, a, b0, b1)                                                  \
    asm volatile(                                                               \
        "mma.sync.aligned.m16n8k16.row.col.f32.f16.f16.f32 "                    \
        "{%0,%1,%2,%3}, {%4,%5,%6,%7}, {%8,%9}, {%0,%1,%2,%3};"                 \
        : "+f"((d)[0]), "+f"((d)[1]), "+f"((d)[2]), "+f"((d)[3])                \
        : "r"((a)[0]), "r"((a)[1]), "r"((a)[2]), "r"((a)[3]), "r"(b0), "r"(b1))

// ---------------- merged prep kernel ----------------
#define PREP_A_BLOCKS (M_TOTAL / 8)                      // 2048
#define PREP_B_BLOCKS ((N_TOTAL * K_TOTAL) / (4 * 256))  // 4096
__global__ void __launch_bounds__(256) prep_kernel(const float* __restrict__ x,
                                                   const float* __restrict__ w,
                                                   const float* __restrict__ c1,
                                                   const float* __restrict__ c2) {
    if (blockIdx.x < PREP_A_BLOCKS) {
        const int row = blockIdx.x * 8 + (threadIdx.x >> 5);
        const int lane = threadIdx.x & 31;
        const float4* src = reinterpret_cast<const float4*>(x + (size_t)row * K_TOTAL);
        uint2* dst = reinterpret_cast<uint2*>(g_A + (size_t)row * K_TOTAL);
        float s = 0.f;
        #pragma unroll
        for (int j = 0; j < 8; j++) {
            const float4 v = src[lane + 32 * j];
            __half2 h01 = __floats2half2_rn(v.x, v.y);
            __half2 h23 = __floats2half2_rn(v.z, v.w);
            uint2 o;
            o.x = *reinterpret_cast<uint32_t*>(&h01);
            o.y = *reinterpret_cast<uint32_t*>(&h23);
            dst[lane + 32 * j] = o;
            s += (v.x + v.y) + (v.z + v.w);
        }
        #pragma unroll
        for (int o = 16; o > 0; o >>= 1) s += __shfl_xor_sync(0xffffffffu, s, o);
        if (lane == 0) g_rowsum[row] = s;
    } else {
        const float a = c1[0], b = c2[0];
        const float mid = fmaxf(a, b) - fminf(a, b);
        const size_t i = (size_t)(blockIdx.x - PREP_A_BLOCKS) * 256 + threadIdx.x;
        const float4 v = reinterpret_cast<const float4*>(w)[i];
        __half2 h01 = __floats2half2_rn(v.x < mid ? 0.f : 1.f, v.y < mid ? 0.f : 1.f);
        __half2 h23 = __floats2half2_rn(v.z < mid ? 0.f : 1.f, v.w < mid ? 0.f : 1.f);
        __half2* dst = reinterpret_cast<__half2*>(g_B) + i * 2;
        dst[0] = h01;
        dst[1] = h23;
    }
}

// ---------------- stage loader ----------------
// Per stage: A = 128 rows x 32 halfs (512 x 16B), B same. 4 chunks per thread
// per operand (128 threads).
__device__ __forceinline__ void load_stage(int s, int kt, int m0, int n0,
                                           uint32_t sb, int tid) {
    const int k0 = kt * BK;
    const uint32_t sa = sb + OFF_STG + s * STG_BYTES + OFF_A;
    #pragma unroll
    for (int i = 0; i < 4; i++) {
        const int idx = tid + i * THREADS;
        const int r = idx >> 2, c = idx & 3;
        cp_async16(sa + r * ROW_B + c * 16,
                   g_A + (size_t)(m0 + r) * K_TOTAL + k0 + c * 8);
    }
    const uint32_t sbB = sb + OFF_STG + s * STG_BYTES + OFF_B;
    #pragma unroll
    for (int i = 0; i < 4; i++) {
        const int idx = tid + i * THREADS;
        const int r = idx >> 2, c = idx & 3;
        cp_async16(sbB + r * ROW_B + c * 16,
                   g_B + (size_t)(n0 + r) * K_TOTAL + k0 + c * 8);
    }
}

// ---------------- main GEMM (mbarrier-decoupled, 3 CTAs/SM) ----------------
__global__ void __launch_bounds__(THREADS, 3) gemm_kernel(const float* __restrict__ c1,
                                                          const float* __restrict__ c2,
                                                          const float* __restrict__ bias,
                                                          float* __restrict__ out) {
    extern __shared__ char smem[];
    const uint32_t sb = smem_u32(smem);
    const int tid = threadIdx.x;
    const int lane = tid & 31, wid = tid >> 5;
    const int wm = wid >> 1, wn = wid & 1;          // 2 x 2 warp grid, warp tile 64x64
    const int m0 = blockIdx.y * BM;
    const int n0 = blockIdx.x * BN;

    if (tid == 0) {
        #pragma unroll
        for (int i = 0; i < STAGES; i++) {
            MBAR_INIT(sb + OFF_FULL + 8 * i, THREADS);
            MBAR_INIT(sb + OFF_EMPTY + 8 * i, THREADS);
        }
    }
    __syncthreads();   // only block-wide barrier in the kernel

    // prologue: prefill 2 stages
    #pragma unroll
    for (int sidx = 0; sidx < STAGES - 1; sidx++) {
        load_stage(sidx, sidx, m0, n0, sb, tid);
        CP_ASYNC_MBAR_ARRIVE(sb + OFF_FULL + 8 * sidx);
    }

    float acc[4][8][4];
    #pragma unroll
    for (int i = 0; i < 4; i++)
        #pragma unroll
        for (int j = 0; j < 8; j++)
            #pragma unroll
            for (int q = 0; q < 4; q++) acc[i][j][q] = 0.f;

    // ldmatrix lane addressing (stage-0 base; stage offset added per iter)
    const uint32_t aAddr = sb + OFF_STG + OFF_A +
        (wm * 64 + (lane & 15)) * ROW_B + (lane >> 4) * 16;
    const uint32_t bAddr = sb + OFF_STG + OFF_B +
        (wn * 64 + (lane & 7) + ((lane >> 4) << 3)) * ROW_B + (((lane >> 3) & 1) * 16);

    // single-buffered frags; B loaded in two 8-reg halves to stay under 170 regs
    uint32_t a[4][4], bh[2][4];

    for (int kt = 0; kt < NKT; kt++) {
        const int s = kt % STAGES;
        MBAR_WAIT_PARITY(sb + OFF_FULL + 8 * s, (kt / STAGES) & 1);

        const uint32_t aS = aAddr + s * STG_BYTES;
        const uint32_t bS = bAddr + s * STG_BYTES;
        #pragma unroll
        for (int ks = 0; ks < 2; ks++) {           // 2 x K=16 per BK=32
            #pragma unroll
            for (int mi = 0; mi < 4; mi++)
                LDSM4(a[mi][0], a[mi][1], a[mi][2], a[mi][3],
                      aS + mi * (16 * ROW_B) + ks * 32);
            // half 1: n = [0,32)
            #pragma unroll
            for (int nj = 0; nj < 2; nj++)
                LDSM4(bh[nj][0], bh[nj][1], bh[nj][2], bh[nj][3],
                      bS + nj * (16 * ROW_B) + ks * 32);
            #pragma unroll
            for (int mi = 0; mi < 4; mi++)
                #pragma unroll
                for (int ni = 0; ni < 4; ni++)
                    MMA16816(acc[mi][ni], a[mi],
                             bh[ni >> 1][(ni & 1) * 2], bh[ni >> 1][(ni & 1) * 2 + 1]);
            // half 2: n = [32,64)
            #pragma unroll
            for (int nj = 0; nj < 2; nj++)
                LDSM4(bh[nj][0], bh[nj][1], bh[nj][2], bh[nj][3],
                      bS + (nj + 2) * (16 * ROW_B) + ks * 32);
            #pragma unroll
            for (int mi = 0; mi < 4; mi++)
                #pragma unroll
                for (int ni = 4; ni < 8; ni++)
                    MMA16816(acc[mi][ni], a[mi],
                             bh[(ni - 4) >> 1][(ni & 1) * 2], bh[(ni - 4) >> 1][(ni & 1) * 2 + 1]);
        }

        MBAR_ARRIVE(sb + OFF_EMPTY + 8 * s);

        const int j = kt + STAGES - 1;
        if (j < NKT) {
            const int sj = j % STAGES;
            if (j >= STAGES)
                MBAR_WAIT_PARITY(sb + OFF_EMPTY + 8 * sj, ((j - STAGES) / STAGES) & 1);
            load_stage(sj, j, m0, n0, sb, tid);
            CP_ASYNC_MBAR_ARRIVE(sb + OFF_FULL + 8 * sj);
        }
    }

    // ---------------- epilogue: out = dd*acc + lower*rowsum + bias ----------
    const float C1 = c1[0], C2 = c2[0];
    const float low = fminf(C1, C2);
    const float dd = fmaxf(C1, C2) - low;

    #pragma unroll
    for (int mi = 0; mi < 4; mi++) {
        const int r0 = m0 + wm * 64 + mi * 16 + (lane >> 2);
        const int r1 = r0 + 8;
        const float rs0 = low * g_rowsum[r0];
        const float rs1 = low * g_rowsum[r1];
        float* o0 = out + (size_t)r0 * N_TOTAL;
        float* o1 = out + (size_t)r1 * N_TOTAL;
        #pragma unroll
        for (int ni = 0; ni < 8; ni++) {
            const int n = n0 + wn * 64 + ni * 8 + (lane & 3) * 2;
            const float2 bv = *reinterpret_cast<const float2*>(bias + n);
            float2 v0, v1;
            v0.x = fmaf(dd, acc[mi][ni][0], rs0 + bv.x);
            v0.y = fmaf(dd, acc[mi][ni][1], rs0 + bv.y);
            v1.x = fmaf(dd, acc[mi][ni][2], rs1 + bv.x);
            v1.y = fmaf(dd, acc[mi][ni][3], rs1 + bv.y);
            *reinterpret_cast<float2*>(o0 + n) = v0;
            *reinterpret_cast<float2*>(o1 + n) = v1;
        }
    }
}

// ---------------- launch ----------------
extern "C" void kernel_launch(void* const* d_in, const int* in_sizes, int n_in,
                              void* d_out, int out_size) {
    const float* input_  = (const float*)d_in[0];
    const float* weights = (const float*)d_in[1];
    const float* c1      = (const float*)d_in[2];
    const float* c2      = (const float*)d_in[3];
    const float* bias    = (const float*)d_in[4];
    float* out = (float*)d_out;

    prep_kernel<<<PREP_A_BLOCKS + PREP_B_BLOCKS, 256>>>(input_, weights, c1, c2);

    cudaFuncSetAttribute(gemm_kernel, cudaFuncAttributeMaxDynamicSharedMemorySize, SMEM_TOTAL);
    dim3 grid(N_TOTAL / BN, M_TOTAL / BM);   // 32 x 128 = 4096 CTAs
    gemm_kernel<<<grid, THREADS, SMEM_TOTAL>>>(c1, c2, bias, out);
}

// round 17
// speedup vs baseline: 1.1269x; 1.1269x over previous
#include <cuda_runtime.h>
#include <cuda_fp16.h>
#include <cstdint>
#include <cstddef>

// ---------------- problem dims (fixed) ----------------
#define M_TOTAL 16384   // B*S = 4*4096
#define N_TOTAL 4096    // DOUT
#define K_TOTAL 1024    // DIN

// ---------------- GEMM tiling: R15 config (best: 346us) made PERSISTENT ----
// 128x128x64, 4 warps, warp tile 64x64, 3-stage mbarrier ring, frag dbl-buf.
// Persistent CTAs (2 x numSMs) loop over tiles; the producer/consumer chunk
// stream and parity cursors continue ACROSS tile boundaries, so the next
// tile's loads overlap the current tile's tail MMAs + epilogue. Removes the
// per-tile pipeline refill, wave quantization, and wave transitions.
#define BM 128
#define BN 128
#define BK 64
#define NKT (K_TOTAL / BK)        // 16 chunks per tile
#define NTILES ((M_TOTAL / BM) * (N_TOTAL / BN))   // 4096
#define STAGES 3
#define THREADS 128               // 4 warps, 2x2 grid, warp tile 64x64

#define ROW_B 144                 // 128B row + 16B pad: LDSM & STS conflict-free
#define A_STG (BM * ROW_B)        // 18432 B
#define B_STG (BN * ROW_B)        // 18432 B
#define STG_BYTES (A_STG + B_STG) // 36864 B
#define OFF_FULL  0               // full[0..2]  mbarriers (8B each)
#define OFF_EMPTY 24              // empty[0..2] mbarriers
#define OFF_STG   128
#define OFF_A 0
#define OFF_B A_STG
#define SMEM_TOTAL (OFF_STG + STAGES * STG_BYTES)   // 110720 -> 2 CTAs/SM

// ---------------- scratch (device globals; allocation forbidden) -----------
__device__ __align__(128) __half g_A[(size_t)M_TOTAL * K_TOTAL];  // 32 MB fp16 input
__device__ __align__(128) __half g_B[(size_t)N_TOTAL * K_TOTAL];  // 8 MB fp16 {0,1} mask
__device__ float g_rowsum[M_TOTAL];

// ---------------- PTX helpers ----------------
__device__ __forceinline__ uint32_t smem_u32(const void* p) {
    uint32_t a;
    asm("{ .reg .u64 t; cvta.to.shared.u64 t, %1; cvt.u32.u64 %0, t; }" : "=r"(a) : "l"(p));
    return a;
}

__device__ __forceinline__ void cp_async16(uint32_t saddr, const void* g) {
    asm volatile("cp.async.cg.shared.global [%0], [%1], 16;" :: "r"(saddr), "l"(g) : "memory");
}

#define MBAR_INIT(addr, cnt)                                                    \
    asm volatile("mbarrier.init.shared.b64 [%0], %1;"                           \
                 :: "r"((uint32_t)(addr)), "r"((uint32_t)(cnt)) : "memory")

#define MBAR_ARRIVE(addr)                                                       \
    asm volatile("mbarrier.arrive.shared.b64 _, [%0];"                          \
                 :: "r"((uint32_t)(addr)) : "memory")

// .noinc: this thread's prior cp.asyncs perform ONE real arrive (consuming the
// init count) on the mbarrier when they complete.
#define CP_ASYNC_MBAR_ARRIVE(addr)                                              \
    asm volatile("cp.async.mbarrier.arrive.noinc.shared.b64 [%0];"              \
                 :: "r"((uint32_t)(addr)) : "memory")

#define MBAR_WAIT_PARITY(addr, par) do {                                        \
    uint32_t _mb = (uint32_t)(addr);                                            \
    uint32_t _p  = (uint32_t)(par);                                             \
    asm volatile(                                                               \
        "{\n\t"                                                                 \
        ".reg .pred P1;\n\t"                                                    \
        "WAIT_LOOP_%=:\n\t"                                                     \
        "mbarrier.try_wait.parity.acquire.cta.shared::cta.b64 P1, [%0], %1, 0x989680;\n\t" \
        "@P1 bra.uni WAIT_DONE_%=;\n\t"                                         \
        "bra.uni WAIT_LOOP_%=;\n\t"                                             \
        "WAIT_DONE_%=:\n\t"                                                     \
        "}" :: "r"(_mb), "r"(_p) : "memory");                                   \
} while (0)

#define LDSM4(r0, r1, r2, r3, addr)                                             \
    asm volatile("ldmatrix.sync.aligned.m8n8.x4.shared.b16 {%0,%1,%2,%3}, [%4];" \
                 : "=r"(r0), "=r"(r1), "=r"(r2), "=r"(r3) : "r"(addr))

#define MMA16816(d, a, b0, b1)                                                  \
    asm volatile(                                                               \
        "mma.sync.aligned.m16n8k16.row.col.f32.f16.f16.f32 "                    \
        "{%0,%1,%2,%3}, {%4,%5,%6,%7}, {%8,%9}, {%0,%1,%2,%3};"                 \
        : "+f"((d)[0]), "+f"((d)[1]), "+f"((d)[2]), "+f"((d)[3])                \
        : "r"((a)[0]), "r"((a)[1]), "r"((a)[2]), "r"((a)[3]), "r"(b0), "r"(b1))

// ---------------- merged prep kernel ----------------
#define PREP_A_BLOCKS (M_TOTAL / 8)                      // 2048
#define PREP_B_BLOCKS ((N_TOTAL * K_TOTAL) / (4 * 256))  // 4096
__global__ void __launch_bounds__(256) prep_kernel(const float* __restrict__ x,
                                                   const float* __restrict__ w,
                                                   const float* __restrict__ c1,
                                                   const float* __restrict__ c2) {
    if (blockIdx.x < PREP_A_BLOCKS) {
        const int row = blockIdx.x * 8 + (threadIdx.x >> 5);
        const int lane = threadIdx.x & 31;
        const float4* src = reinterpret_cast<const float4*>(x + (size_t)row * K_TOTAL);
        uint2* dst = reinterpret_cast<uint2*>(g_A + (size_t)row * K_TOTAL);
        float s = 0.f;
        #pragma unroll
        for (int j = 0; j < 8; j++) {
            const float4 v = src[lane + 32 * j];
            __half2 h01 = __floats2half2_rn(v.x, v.y);
            __half2 h23 = __floats2half2_rn(v.z, v.w);
            uint2 o;
            o.x = *reinterpret_cast<uint32_t*>(&h01);
            o.y = *reinterpret_cast<uint32_t*>(&h23);
            dst[lane + 32 * j] = o;
            s += (v.x + v.y) + (v.z + v.w);
        }
        #pragma unroll
        for (int o = 16; o > 0; o >>= 1) s += __shfl_xor_sync(0xffffffffu, s, o);
        if (lane == 0) g_rowsum[row] = s;
    } else {
        const float a = c1[0], b = c2[0];
        const float mid = fmaxf(a, b) - fminf(a, b);
        const size_t i = (size_t)(blockIdx.x - PREP_A_BLOCKS) * 256 + threadIdx.x;
        const float4 v = reinterpret_cast<const float4*>(w)[i];
        __half2 h01 = __floats2half2_rn(v.x < mid ? 0.f : 1.f, v.y < mid ? 0.f : 1.f);
        __half2 h23 = __floats2half2_rn(v.z < mid ? 0.f : 1.f, v.w < mid ? 0.f : 1.f);
        __half2* dst = reinterpret_cast<__half2*>(g_B) + i * 2;
        dst[0] = h01;
        dst[1] = h23;
    }
}

// ---------------- stage loader ----------------
// tile -> (m0, n0): m0 = (tile>>5)*128, n0 = (tile&31)*128
__device__ __forceinline__ void load_stage(int s, int kt, int tile,
                                           uint32_t sb, int tid) {
    const int m0 = (tile >> 5) << 7;
    const int n0 = (tile & 31) << 7;
    const int k0 = kt * BK;
    const uint32_t sa = sb + OFF_STG + s * STG_BYTES + OFF_A;
    #pragma unroll
    for (int i = 0; i < 8; i++) {
        const int idx = tid + i * THREADS;
        const int r = idx >> 3, c = idx & 7;
        cp_async16(sa + r * ROW_B + c * 16,
                   g_A + (size_t)(m0 + r) * K_TOTAL + k0 + c * 8);
    }
    const uint32_t sbB = sb + OFF_STG + s * STG_BYTES + OFF_B;
    #pragma unroll
    for (int i = 0; i < 8; i++) {
        const int idx = tid + i * THREADS;
        const int r = idx >> 3, c = idx & 7;
        cp_async16(sbB + r * ROW_B + c * 16,
                   g_B + (size_t)(n0 + r) * K_TOTAL + k0 + c * 8);
    }
}

// ---------------- main GEMM (persistent, mbarrier ring across tiles) -------
__global__ void __launch_bounds__(THREADS, 2) gemm_kernel(const float* __restrict__ c1,
                                                          const float* __restrict__ c2,
                                                          const float* __restrict__ bias,
                                                          float* __restrict__ out) {
    extern __shared__ char smem[];
    const uint32_t sb = smem_u32(smem);
    const int tid = threadIdx.x;
    const int lane = tid & 31, wid = tid >> 5;
    const int wm = wid >> 1, wn = wid & 1;          // 2 x 2 warp grid, warp tile 64x64
    const int G = gridDim.x;

    if (tid == 0) {
        #pragma unroll
        for (int i = 0; i < STAGES; i++) {
            MBAR_INIT(sb + OFF_FULL + 8 * i, THREADS);
            MBAR_INIT(sb + OFF_EMPTY + 8 * i, THREADS);
        }
    }
    __syncthreads();   // only block-wide barrier in the kernel

    // ldmatrix lane addressing (stage-0 base; stage offset added per chunk)
    const uint32_t aAddr = sb + OFF_STG + OFF_A +
        (wm * 64 + (lane & 15)) * ROW_B + (lane >> 4) * 16;
    const uint32_t bAddr = sb + OFF_STG + OFF_B +
        (wn * 64 + (lane & 7) + ((lane >> 4) << 3)) * ROW_B + (((lane >> 3) & 1) * 16);

    const float C1 = c1[0], C2 = c2[0];
    const float low = fminf(C1, C2);
    const float dd = fmaxf(C1, C2) - low;

    // ---- persistent state: continuous chunk stream across tiles ----
    int ctile = blockIdx.x;           // consumer tile
    if (ctile >= NTILES) return;
    int ptile = blockIdx.x;           // producer tile
    int pkt = 2;                      // next chunk within ptile (0,1 preloaded)
    int pstage = 2;                   // stage for next producer load
    int cstage = 0, cphase = 0;       // consumer full-wait cursor
    int estage = 0, ephase = 0;       // producer empty-wait cursor
    int first_pchunk = 1;             // chunk 2 targets virgin stage 2: no wait

    // prologue: chunks 0,1 of first tile into stages 0,1
    load_stage(0, 0, ctile, sb, tid);
    CP_ASYNC_MBAR_ARRIVE(sb + OFF_FULL + 0);
    load_stage(1, 1, ctile, sb, tid);
    CP_ASYNC_MBAR_ARRIVE(sb + OFF_FULL + 8);

    uint32_t a[2][4][4], b[2][4][4];  // double-buffered fragments

#define LOAD_FRAGS(buf, aS, bS, ks)                                             \
    do {                                                                        \
        _Pragma("unroll")                                                       \
        for (int mi = 0; mi < 4; mi++)                                          \
            LDSM4(a[buf][mi][0], a[buf][mi][1], a[buf][mi][2], a[buf][mi][3],   \
                  (aS) + mi * (16 * ROW_B) + (ks) * 32);                        \
        _Pragma("unroll")                                                       \
        for (int nj = 0; nj < 4; nj++)                                          \
            LDSM4(b[buf][nj][0], b[buf][nj][1], b[buf][nj][2], b[buf][nj][3],   \
                  (bS) + nj * (16 * ROW_B) + (ks) * 32);                        \
    } while (0)

    while (true) {
        float acc[4][8][4];
        #pragma unroll
        for (int i = 0; i < 4; i++)
            #pragma unroll
            for (int j = 0; j < 8; j++)
                #pragma unroll
                for (int q = 0; q < 4; q++) acc[i][j][q] = 0.f;

        for (int kt = 0; kt < NKT; kt++) {
            const int s = cstage;
            MBAR_WAIT_PARITY(sb + OFF_FULL + 8 * s, cphase);
            if (++cstage == STAGES) { cstage = 0; cphase ^= 1; }

            const uint32_t aS = aAddr + s * STG_BYTES;
            const uint32_t bS = bAddr + s * STG_BYTES;
            LOAD_FRAGS(0, aS, bS, 0);
            #pragma unroll
            for (int ks = 0; ks < 4; ks++) {   // 4 x K=16 per BK=64
                const int cur = ks & 1;
                if (ks < 3) LOAD_FRAGS(cur ^ 1, aS, bS, ks + 1);
                #pragma unroll
                for (int mi = 0; mi < 4; mi++)
                    #pragma unroll
                    for (int ni = 0; ni < 8; ni++)
                        MMA16816(acc[mi][ni], a[cur][mi],
                                 b[cur][ni >> 1][(ni & 1) * 2],
                                 b[cur][ni >> 1][(ni & 1) * 2 + 1]);
            }

            MBAR_ARRIVE(sb + OFF_EMPTY + 8 * s);

            // producer: next chunk in the continuous stream (may cross tiles)
            if (ptile < NTILES) {
                if (first_pchunk) {
                    first_pchunk = 0;
                } else {
                    MBAR_WAIT_PARITY(sb + OFF_EMPTY + 8 * estage, ephase);
                    if (++estage == STAGES) { estage = 0; ephase ^= 1; }
                }
                load_stage(pstage, pkt, ptile, sb, tid);
                CP_ASYNC_MBAR_ARRIVE(sb + OFF_FULL + 8 * pstage);
                if (++pstage == STAGES) pstage = 0;
                if (++pkt == NKT) { pkt = 0; ptile += G; }
            }
        }

        // ---- epilogue for ctile (overlaps in-flight next-tile cp.asyncs) ----
        const int m0 = (ctile >> 5) << 7;
        const int n0 = (ctile & 31) << 7;
        #pragma unroll
        for (int mi = 0; mi < 4; mi++) {
            const int r0 = m0 + wm * 64 + mi * 16 + (lane >> 2);
            const int r1 = r0 + 8;
            const float rs0 = low * g_rowsum[r0];
            const float rs1 = low * g_rowsum[r1];
            float* o0 = out + (size_t)r0 * N_TOTAL;
            float* o1 = out + (size_t)r1 * N_TOTAL;
            #pragma unroll
            for (int ni = 0; ni < 8; ni++) {
                const int n = n0 + wn * 64 + ni * 8 + (lane & 3) * 2;
                const float2 bv = *reinterpret_cast<const float2*>(bias + n);
                float2 v0, v1;
                v0.x = fmaf(dd, acc[mi][ni][0], rs0 + bv.x);
                v0.y = fmaf(dd, acc[mi][ni][1], rs0 + bv.y);
                v1.x = fmaf(dd, acc[mi][ni][2], rs1 + bv.x);
                v1.y = fmaf(dd, acc[mi][ni][3], rs1 + bv.y);
                *reinterpret_cast<float2*>(o0 + n) = v0;
                *reinterpret_cast<float2*>(o1 + n) = v1;
            }
        }

        ctile += G;
        if (ctile >= NTILES) break;
    }
}

// ---------------- launch ----------------
extern "C" void kernel_launch(void* const* d_in, const int* in_sizes, int n_in,
                              void* d_out, int out_size) {
    const float* input_  = (const float*)d_in[0];
    const float* weights = (const float*)d_in[1];
    const float* c1      = (const float*)d_in[2];
    const float* c2      = (const float*)d_in[3];
    const float* bias    = (const float*)d_in[4];
    float* out = (float*)d_out;

    prep_kernel<<<PREP_A_BLOCKS + PREP_B_BLOCKS, 256>>>(input_, weights, c1, c2);

    int dev = 0, nsm = 148;
    cudaGetDevice(&dev);
    cudaDeviceGetAttribute(&nsm, cudaDevAttrMultiProcessorCount, dev);

    cudaFuncSetAttribute(gemm_kernel, cudaFuncAttributeMaxDynamicSharedMemorySize, SMEM_TOTAL);
    gemm_kernel<<<2 * nsm, THREADS, SMEM_TOTAL>>>(c1, c2, bias, out);
}